// round 5
// baseline (speedup 1.0000x reference)
#include <cuda_runtime.h>
#include <cuda_fp16.h>
#include <cstdint>

#define DEV __device__ __forceinline__

// ============================ constants ============================
static constexpr int NTILES   = 2048;   // 262144 / 128
static constexpr int TILE_M   = 128;
static constexpr int NTHREADS = 256;    // 8 warps, each owns 16 rows
static constexpr int NCTAS    = 296;    // 2 per SM (148 SMs)

// SMEM layout in u32 units.
// Weight fragments, per layer: [n_group][k_step][lane][2] u32 (lane-contiguous -> LDS.64, conflict-free)
static constexpr int SM_L1 = 0;                 // 16 k x 16 n frags  -> 16384 u32
static constexpr int SM_L2 = 16384;             // 8 x 8              -> 4096
static constexpr int SM_L3 = 20480;             // 4 x 4              -> 1024
static constexpr int SM_L4 = 21504;             // 2 x 2              -> 256
static constexpr int SM_L5 = 21760;             // 1 x 1              -> 64
static constexpr int SM_B1 = 21824;             // biases (f32)
static constexpr int SM_B2 = 21952;
static constexpr int SM_B3 = 22016;
static constexpr int SM_B4 = 22048;
static constexpr int SM_B5 = 22064;
static constexpr int SM_B6 = 22072;
static constexpr int SM_B7 = 22076;
static constexpr int SM_W6 = 22080;             // 32 f32 (8x4 row-major)
static constexpr int SM_W7 = 22112;             // 4 f32
static constexpr int SM_U32_TOTAL = 22128;
static constexpr int SMEM_BYTES = SM_U32_TOTAL * 4;   // 88512

// ============================ mma helper ============================
// m16n8k16 f16 x f16 -> f32.  Fragment layout (lane l, g=l>>2, t=l&3):
//   A: a0 = row g   k{2t,2t+1} | a1 = row g+8 k{2t,2t+1} | a2 = row g k{2t+8,2t+9} | a3 = row g+8 k{2t+8,2t+9}
//   B: b0 = k{2t,2t+1} col g   | b1 = k{2t+8,2t+9} col g
//   D: c0 = row g col 2t | c1 = row g col 2t+1 | c2 = row g+8 col 2t | c3 = row g+8 col 2t+1
// Crucial property: D layout == next layer's A layout (cols become k), so
// activations never leave registers between layers.
DEV void mma16816(float d[4], const uint32_t a[4], uint32_t b0, uint32_t b1) {
    asm volatile(
        "mma.sync.aligned.m16n8k16.row.col.f32.f16.f16.f32 "
        "{%0,%1,%2,%3}, {%4,%5,%6,%7}, {%8,%9}, {%0,%1,%2,%3};\n"
        : "+f"(d[0]), "+f"(d[1]), "+f"(d[2]), "+f"(d[3])
        : "r"(a[0]), "r"(a[1]), "r"(a[2]), "r"(a[3]), "r"(b0), "r"(b1));
}

DEV uint32_t pack_h2(float a, float b) {
    __half2 h = __floats2half2_rn(a, b);
    return *reinterpret_cast<uint32_t*>(&h);
}

// ============================ weight prepack ============================
// W stored global as (K, N) row-major (n contiguous).  Destination fragment f = n*KF + k.
template <int K, int N>
DEV void prepack(uint32_t* __restrict__ dst, const float* __restrict__ W, int tid) {
    constexpr int KF = K / 16, NF = N / 8;
    for (int i = tid; i < KF * NF * 64; i += NTHREADS) {
        int f = i >> 6, rem = i & 63, lane = rem >> 1, reg = rem & 1;
        int n = f / KF, kk = f % KF;
        int g = lane >> 2, t = lane & 3;
        int krow = kk * 16 + 2 * t + reg * 8;
        int ncol = n * 8 + g;
        dst[f * 64 + lane * 2 + reg] = pack_h2(W[krow * N + ncol], W[(krow + 1) * N + ncol]);
    }
}

// ============================ generic middle layer ============================
// Ain: packed A fragments (KF k-steps); compute @ weights -> bias+relu -> next A frags.
template <int KF, int NF>
DEV void layer_fwd(const uint32_t* __restrict__ bfrag, const float* __restrict__ bias,
                   const uint32_t* __restrict__ Ain, uint32_t* __restrict__ Aout, int lane) {
    const int t = lane & 3;
    float D[NF][4];
    #pragma unroll
    for (int n = 0; n < NF; ++n) { D[n][0] = D[n][1] = D[n][2] = D[n][3] = 0.f; }
    #pragma unroll
    for (int k = 0; k < KF; ++k) {
        #pragma unroll
        for (int n = 0; n < NF; ++n) {
            uint2 b = *reinterpret_cast<const uint2*>(bfrag + ((n * KF + k) * 32 + lane) * 2);
            mma16816(D[n], Ain + 4 * k, b.x, b.y);
        }
    }
    #pragma unroll
    for (int n = 0; n < NF; ++n) {
        float bb0 = bias[8 * n + 2 * t], bb1 = bias[8 * n + 2 * t + 1];
        uint32_t lo = pack_h2(fmaxf(D[n][0] + bb0, 0.f), fmaxf(D[n][1] + bb1, 0.f));  // row g
        uint32_t hi = pack_h2(fmaxf(D[n][2] + bb0, 0.f), fmaxf(D[n][3] + bb1, 0.f));  // row g+8
        // Next layer A fragment: k-step = n>>1, reg pair selected by n&1.
        Aout[(n >> 1) * 4 + (n & 1) * 2 + 0] = lo;
        Aout[(n >> 1) * 4 + (n & 1) * 2 + 1] = hi;
    }
}

// ============================ kernel ============================
__global__ void __launch_bounds__(NTHREADS, 2)
fused_mlp_kernel(const float* __restrict__ x,
                 const float* __restrict__ W1g, const float* __restrict__ b1g,
                 const float* __restrict__ W2g, const float* __restrict__ b2g,
                 const float* __restrict__ W3g, const float* __restrict__ b3g,
                 const float* __restrict__ W4g, const float* __restrict__ b4g,
                 const float* __restrict__ W5g, const float* __restrict__ b5g,
                 const float* __restrict__ W6g, const float* __restrict__ b6g,
                 const float* __restrict__ W7g, const float* __restrict__ b7g,
                 float* __restrict__ out) {
    extern __shared__ uint32_t sm[];
    float* sf = reinterpret_cast<float*>(sm);

    const int tid  = threadIdx.x;
    const int wid  = tid >> 5;
    const int lane = tid & 31;
    const int g    = lane >> 2;
    const int t    = lane & 3;

    // -------- prepack weights into per-fragment SMEM --------
    prepack<256, 128>(sm + SM_L1, W1g, tid);
    prepack<128, 64>(sm + SM_L2, W2g, tid);
    prepack<64, 32>(sm + SM_L3, W3g, tid);
    prepack<32, 16>(sm + SM_L4, W4g, tid);
    prepack<16, 8>(sm + SM_L5, W5g, tid);
    if (tid < 128) sf[SM_B1 + tid] = b1g[tid];
    if (tid < 64)  sf[SM_B2 + tid] = b2g[tid];
    if (tid < 32)  sf[SM_B3 + tid] = b3g[tid];
    if (tid < 16)  sf[SM_B4 + tid] = b4g[tid];
    if (tid < 8)   sf[SM_B5 + tid] = b5g[tid];
    if (tid < 4)   sf[SM_B6 + tid] = b6g[tid];
    if (tid < 1)   sf[SM_B7 + tid] = b7g[tid];
    if (tid < 32)  sf[SM_W6 + tid] = W6g[tid];   // (8,4) row-major
    if (tid < 4)   sf[SM_W7 + tid] = W7g[tid];   // (4,1)
    __syncthreads();

    const float* b1s = sf + SM_B1;
    const float* b2s = sf + SM_B2;
    const float* b3s = sf + SM_B3;
    const float* b4s = sf + SM_B4;
    const float* b5s = sf + SM_B5;
    const float* b6s = sf + SM_B6;
    const float  b7v = sf[SM_B7];
    const float* W6s = sf + SM_W6;
    const float* W7s = sf + SM_W7;

    // -------- main loop: each warp independently pushes its 16 rows through all layers --------
    for (int tile = blockIdx.x; tile < NTILES; tile += gridDim.x) {
        const int row0 = tile * TILE_M + wid * 16;

        // ---- L1: [16 x 256] @ W1 -> 16 x 128 ----
        float D[16][4];
        #pragma unroll
        for (int n = 0; n < 16; ++n) { D[n][0] = D[n][1] = D[n][2] = D[n][3] = 0.f; }

        const float* xr0 = x + (size_t)(row0 + g) * 256 + 2 * t;
        const float* xr1 = xr0 + 8 * 256;
        #pragma unroll
        for (int k = 0; k < 16; ++k) {
            float2 v0 = *reinterpret_cast<const float2*>(xr0 + 16 * k);
            float2 v1 = *reinterpret_cast<const float2*>(xr1 + 16 * k);
            float2 v2 = *reinterpret_cast<const float2*>(xr0 + 16 * k + 8);
            float2 v3 = *reinterpret_cast<const float2*>(xr1 + 16 * k + 8);
            uint32_t A[4];
            A[0] = pack_h2(v0.x, v0.y);
            A[1] = pack_h2(v1.x, v1.y);
            A[2] = pack_h2(v2.x, v2.y);
            A[3] = pack_h2(v3.x, v3.y);
            #pragma unroll
            for (int n = 0; n < 16; ++n) {
                uint2 b = *reinterpret_cast<const uint2*>(sm + SM_L1 + ((n * 16 + k) * 32 + lane) * 2);
                mma16816(D[n], A, b.x, b.y);
            }
        }
        uint32_t A2[32];
        #pragma unroll
        for (int n = 0; n < 16; ++n) {
            float bb0 = b1s[8 * n + 2 * t], bb1 = b1s[8 * n + 2 * t + 1];
            A2[(n >> 1) * 4 + (n & 1) * 2 + 0] = pack_h2(fmaxf(D[n][0] + bb0, 0.f), fmaxf(D[n][1] + bb1, 0.f));
            A2[(n >> 1) * 4 + (n & 1) * 2 + 1] = pack_h2(fmaxf(D[n][2] + bb0, 0.f), fmaxf(D[n][3] + bb1, 0.f));
        }

        // ---- L2..L4 ----
        uint32_t A3[16], A4[8], A5[4];
        layer_fwd<8, 8>(sm + SM_L2, b2s, A2, A3, lane);
        layer_fwd<4, 4>(sm + SM_L3, b3s, A3, A4, lane);
        layer_fwd<2, 2>(sm + SM_L4, b4s, A4, A5, lane);

        // ---- L5: [16 x 16] @ W5 -> 16 x 8 ----
        float d5[4] = {0.f, 0.f, 0.f, 0.f};
        {
            uint2 b = *reinterpret_cast<const uint2*>(sm + SM_L5 + lane * 2);
            mma16816(d5, A5, b.x, b.y);
        }

        // ---- L6 + L7 + sigmoid (scalar, 4-lane butterfly per row) ----
        float h0 = fmaxf(d5[0] + b5s[2 * t], 0.f);       // row g,   col 2t   (= h5[2t])
        float h1 = fmaxf(d5[1] + b5s[2 * t + 1], 0.f);   // row g,   col 2t+1
        float h2 = fmaxf(d5[2] + b5s[2 * t], 0.f);       // row g+8, col 2t
        float h3 = fmaxf(d5[3] + b5s[2 * t + 1], 0.f);   // row g+8, col 2t+1

        float pa[4], pb[4];
        #pragma unroll
        for (int j = 0; j < 4; ++j) {
            pa[j] = h0 * W6s[(2 * t) * 4 + j] + h1 * W6s[(2 * t + 1) * 4 + j];
            pb[j] = h2 * W6s[(2 * t) * 4 + j] + h3 * W6s[(2 * t + 1) * 4 + j];
        }
        #pragma unroll
        for (int mask = 1; mask <= 2; mask <<= 1) {
            #pragma unroll
            for (int j = 0; j < 4; ++j) {
                pa[j] += __shfl_xor_sync(0xFFFFFFFFu, pa[j], mask);
                pb[j] += __shfl_xor_sync(0xFFFFFFFFu, pb[j], mask);
            }
        }
        float za = b7v, zb = b7v;
        #pragma unroll
        for (int j = 0; j < 4; ++j) {
            za += fmaxf(pa[j] + b6s[j], 0.f) * W7s[j];
            zb += fmaxf(pb[j] + b6s[j], 0.f) * W7s[j];
        }
        if (t == 0) {
            float* o = out + row0;
            o[g]     = 1.0f / (1.0f + __expf(-za));
            o[g + 8] = 1.0f / (1.0f + __expf(-zb));
        }
    }
}

// ============================ launch ============================
extern "C" void kernel_launch(void* const* d_in, const int* in_sizes, int n_in,
                              void* d_out, int out_size) {
    cudaFuncSetAttribute(fused_mlp_kernel,
                         cudaFuncAttributeMaxDynamicSharedMemorySize, SMEM_BYTES);
    fused_mlp_kernel<<<NCTAS, NTHREADS, SMEM_BYTES>>>(
        (const float*)d_in[0],
        (const float*)d_in[1],  (const float*)d_in[2],
        (const float*)d_in[3],  (const float*)d_in[4],
        (const float*)d_in[5],  (const float*)d_in[6],
        (const float*)d_in[7],  (const float*)d_in[8],
        (const float*)d_in[9],  (const float*)d_in[10],
        (const float*)d_in[11], (const float*)d_in[12],
        (const float*)d_in[13], (const float*)d_in[14],
        (float*)d_out);
}

// round 6
// speedup vs baseline: 1.1342x; 1.1342x over previous
#include <cuda_runtime.h>
#include <cuda_fp16.h>
#include <cstdint>

#define DEV __device__ __forceinline__

// ============================ constants ============================
static constexpr int NTILES   = 2048;   // 262144 / 128
static constexpr int TILE_M   = 128;
static constexpr int NTHREADS = 256;    // 8 warps, each owns 16 rows
static constexpr int NCTAS    = 296;    // 2 per SM (148 SMs)

// SMEM layout in u32 units.
// Weight fragments, per layer: [n_group][k_step][lane][2] u32 (lane-contiguous -> LDS.64, conflict-free)
static constexpr int SM_L1 = 0;                 // 16 k x 16 n frags  -> 16384 u32
static constexpr int SM_L2 = 16384;             // 8 x 8              -> 4096
static constexpr int SM_L3 = 20480;             // 4 x 4              -> 1024
static constexpr int SM_L4 = 21504;             // 2 x 2              -> 256
static constexpr int SM_L5 = 21760;             // 1 x 1              -> 64
static constexpr int SM_B1 = 21824;             // biases (f32)
static constexpr int SM_B2 = 21952;
static constexpr int SM_B3 = 22016;
static constexpr int SM_B4 = 22048;
static constexpr int SM_B5 = 22064;
static constexpr int SM_B6 = 22072;
static constexpr int SM_B7 = 22076;
static constexpr int SM_W6 = 22080;             // 32 f32 (8x4 row-major)
static constexpr int SM_W7 = 22112;             // 4 f32
static constexpr int SM_U32_TOTAL = 22128;
static constexpr int SMEM_BYTES = SM_U32_TOTAL * 4;   // 88512

// ============================ mma helper ============================
// m16n8k16 f16 x f16 -> f32.  Fragment layout (lane l, g=l>>2, t=l&3):
//   A: a0 = row g   k{2t,2t+1} | a1 = row g+8 k{2t,2t+1} | a2 = row g k{2t+8,2t+9} | a3 = row g+8 k{2t+8,2t+9}
//   B: b0 = k{2t,2t+1} col g   | b1 = k{2t+8,2t+9} col g
//   D: c0 = row g col 2t | c1 = row g col 2t+1 | c2 = row g+8 col 2t | c3 = row g+8 col 2t+1
// D layout == next layer's A layout, so activations stay in registers across layers.
DEV void mma16816(float d[4], const uint32_t a[4], uint32_t b0, uint32_t b1) {
    asm volatile(
        "mma.sync.aligned.m16n8k16.row.col.f32.f16.f16.f32 "
        "{%0,%1,%2,%3}, {%4,%5,%6,%7}, {%8,%9}, {%0,%1,%2,%3};\n"
        : "+f"(d[0]), "+f"(d[1]), "+f"(d[2]), "+f"(d[3])
        : "r"(a[0]), "r"(a[1]), "r"(a[2]), "r"(a[3]), "r"(b0), "r"(b1));
}

DEV uint32_t pack_h2(float a, float b) {
    __half2 h = __floats2half2_rn(a, b);
    return *reinterpret_cast<uint32_t*>(&h);
}

// ============================ weight prepack ============================
// W stored global as (K, N) row-major (n contiguous).  Destination fragment f = n*KF + k.
//
// PERM_K: layer-1-only K permutation so the x loader can use contiguous LDG.128:
//   fragment k-col (2t + 8r + j)  <->  global k-col (4t + 2r + j),  t=0..3, r,j=0..1
// Within a k-step, lane t's four needed elements {2t,2t+1,2t+8,2t+9} become the
// contiguous global cols {4t..4t+3} = one float4.  Weights here get the inverse map.
template <int K, int N, bool PERM_K>
DEV void prepack(uint32_t* __restrict__ dst, const float* __restrict__ W, int tid) {
    constexpr int KF = K / 16, NF = N / 8;
    for (int i = tid; i < KF * NF * 64; i += NTHREADS) {
        int f = i >> 6, rem = i & 63, lane = rem >> 1, reg = rem & 1;
        int n = f / KF, kk = f % KF;
        int g = lane >> 2, t = lane & 3;
        int krow = PERM_K ? (kk * 16 + 4 * t + 2 * reg)     // pairs (4t+2r, 4t+2r+1)
                          : (kk * 16 + 2 * t + 8 * reg);    // pairs (2t+8r, 2t+8r+1)
        int ncol = n * 8 + g;
        dst[f * 64 + lane * 2 + reg] = pack_h2(W[krow * N + ncol], W[(krow + 1) * N + ncol]);
    }
}

// ============================ generic middle layer ============================
// Ain: packed A fragments (KF k-steps); compute @ weights -> bias+relu -> next A frags.
template <int KF, int NF>
DEV void layer_fwd(const uint32_t* __restrict__ bfrag, const float* __restrict__ bias,
                   const uint32_t* __restrict__ Ain, uint32_t* __restrict__ Aout, int lane) {
    const int t = lane & 3;
    float D[NF][4];
    #pragma unroll
    for (int n = 0; n < NF; ++n) { D[n][0] = D[n][1] = D[n][2] = D[n][3] = 0.f; }
    #pragma unroll
    for (int k = 0; k < KF; ++k) {
        #pragma unroll
        for (int n = 0; n < NF; ++n) {
            uint2 b = *reinterpret_cast<const uint2*>(bfrag + ((n * KF + k) * 32 + lane) * 2);
            mma16816(D[n], Ain + 4 * k, b.x, b.y);
        }
    }
    #pragma unroll
    for (int n = 0; n < NF; ++n) {
        float bb0 = bias[8 * n + 2 * t], bb1 = bias[8 * n + 2 * t + 1];
        uint32_t lo = pack_h2(fmaxf(D[n][0] + bb0, 0.f), fmaxf(D[n][1] + bb1, 0.f));  // row g
        uint32_t hi = pack_h2(fmaxf(D[n][2] + bb0, 0.f), fmaxf(D[n][3] + bb1, 0.f));  // row g+8
        Aout[(n >> 1) * 4 + (n & 1) * 2 + 0] = lo;
        Aout[(n >> 1) * 4 + (n & 1) * 2 + 1] = hi;
    }
}

// ============================ kernel ============================
__global__ void __launch_bounds__(NTHREADS, 2)
fused_mlp_kernel(const float* __restrict__ x,
                 const float* __restrict__ W1g, const float* __restrict__ b1g,
                 const float* __restrict__ W2g, const float* __restrict__ b2g,
                 const float* __restrict__ W3g, const float* __restrict__ b3g,
                 const float* __restrict__ W4g, const float* __restrict__ b4g,
                 const float* __restrict__ W5g, const float* __restrict__ b5g,
                 const float* __restrict__ W6g, const float* __restrict__ b6g,
                 const float* __restrict__ W7g, const float* __restrict__ b7g,
                 float* __restrict__ out) {
    extern __shared__ uint32_t sm[];
    float* sf = reinterpret_cast<float*>(sm);

    const int tid  = threadIdx.x;
    const int wid  = tid >> 5;
    const int lane = tid & 31;
    const int g    = lane >> 2;
    const int t    = lane & 3;

    // -------- prepack weights into per-fragment SMEM --------
    prepack<256, 128, true >(sm + SM_L1, W1g, tid);   // K-permuted (matches LDG.128 x path)
    prepack<128, 64,  false>(sm + SM_L2, W2g, tid);
    prepack<64,  32,  false>(sm + SM_L3, W3g, tid);
    prepack<32,  16,  false>(sm + SM_L4, W4g, tid);
    prepack<16,  8,   false>(sm + SM_L5, W5g, tid);
    if (tid < 128) sf[SM_B1 + tid] = b1g[tid];
    if (tid < 64)  sf[SM_B2 + tid] = b2g[tid];
    if (tid < 32)  sf[SM_B3 + tid] = b3g[tid];
    if (tid < 16)  sf[SM_B4 + tid] = b4g[tid];
    if (tid < 8)   sf[SM_B5 + tid] = b5g[tid];
    if (tid < 4)   sf[SM_B6 + tid] = b6g[tid];
    if (tid < 1)   sf[SM_B7 + tid] = b7g[tid];
    if (tid < 32)  sf[SM_W6 + tid] = W6g[tid];   // (8,4) row-major
    if (tid < 4)   sf[SM_W7 + tid] = W7g[tid];   // (4,1)
    __syncthreads();

    const float* b1s = sf + SM_B1;
    const float* b2s = sf + SM_B2;
    const float* b3s = sf + SM_B3;
    const float* b4s = sf + SM_B4;
    const float* b5s = sf + SM_B5;
    const float* b6s = sf + SM_B6;
    const float  b7v = sf[SM_B7];
    const float* W6s = sf + SM_W6;
    const float* W7s = sf + SM_W7;

    // -------- main loop: each warp independently pushes its 16 rows through all layers --------
    for (int tile = blockIdx.x; tile < NTILES; tile += gridDim.x) {
        const int row0 = tile * TILE_M + wid * 16;

        // ---- L1: [16 x 256] @ W1 -> 16 x 128 ----
        float D[16][4];
        #pragma unroll
        for (int n = 0; n < 16; ++n) { D[n][0] = D[n][1] = D[n][2] = D[n][3] = 0.f; }

        // Lane l reads float4 at (row g, global cols 16k+4t..4t+3) and (row g+8, same).
        // With the K-permutation this IS the A fragment: a0=(x,y), a2=(z,w) / a1,a3 from row g+8.
        const float4* xr0 = reinterpret_cast<const float4*>(x + (size_t)(row0 + g) * 256) + t;
        const float4* xr1 = reinterpret_cast<const float4*>(x + (size_t)(row0 + g + 8) * 256) + t;
        #pragma unroll
        for (int k = 0; k < 16; ++k) {
            float4 v0 = xr0[k * 4];
            float4 v1 = xr1[k * 4];
            uint32_t A[4];
            A[0] = pack_h2(v0.x, v0.y);   // row g,   frag k {2t,2t+1}
            A[1] = pack_h2(v1.x, v1.y);   // row g+8, frag k {2t,2t+1}
            A[2] = pack_h2(v0.z, v0.w);   // row g,   frag k {2t+8,2t+9}
            A[3] = pack_h2(v1.z, v1.w);   // row g+8, frag k {2t+8,2t+9}
            #pragma unroll
            for (int n = 0; n < 16; ++n) {
                uint2 b = *reinterpret_cast<const uint2*>(sm + SM_L1 + ((n * 16 + k) * 32 + lane) * 2);
                mma16816(D[n], A, b.x, b.y);
            }
        }
        uint32_t A2[32];
        #pragma unroll
        for (int n = 0; n < 16; ++n) {
            float bb0 = b1s[8 * n + 2 * t], bb1 = b1s[8 * n + 2 * t + 1];
            A2[(n >> 1) * 4 + (n & 1) * 2 + 0] = pack_h2(fmaxf(D[n][0] + bb0, 0.f), fmaxf(D[n][1] + bb1, 0.f));
            A2[(n >> 1) * 4 + (n & 1) * 2 + 1] = pack_h2(fmaxf(D[n][2] + bb0, 0.f), fmaxf(D[n][3] + bb1, 0.f));
        }

        // ---- L2..L4 ----
        uint32_t A3[16], A4[8], A5[4];
        layer_fwd<8, 8>(sm + SM_L2, b2s, A2, A3, lane);
        layer_fwd<4, 4>(sm + SM_L3, b3s, A3, A4, lane);
        layer_fwd<2, 2>(sm + SM_L4, b4s, A4, A5, lane);

        // ---- L5: [16 x 16] @ W5 -> 16 x 8 ----
        float d5[4] = {0.f, 0.f, 0.f, 0.f};
        {
            uint2 b = *reinterpret_cast<const uint2*>(sm + SM_L5 + lane * 2);
            mma16816(d5, A5, b.x, b.y);
        }

        // ---- L6 + L7 + sigmoid (scalar, 4-lane butterfly per row) ----
        float h0 = fmaxf(d5[0] + b5s[2 * t], 0.f);       // row g,   col 2t
        float h1 = fmaxf(d5[1] + b5s[2 * t + 1], 0.f);   // row g,   col 2t+1
        float h2 = fmaxf(d5[2] + b5s[2 * t], 0.f);       // row g+8, col 2t
        float h3 = fmaxf(d5[3] + b5s[2 * t + 1], 0.f);   // row g+8, col 2t+1

        float pa[4], pb[4];
        #pragma unroll
        for (int j = 0; j < 4; ++j) {
            pa[j] = h0 * W6s[(2 * t) * 4 + j] + h1 * W6s[(2 * t + 1) * 4 + j];
            pb[j] = h2 * W6s[(2 * t) * 4 + j] + h3 * W6s[(2 * t + 1) * 4 + j];
        }
        #pragma unroll
        for (int mask = 1; mask <= 2; mask <<= 1) {
            #pragma unroll
            for (int j = 0; j < 4; ++j) {
                pa[j] += __shfl_xor_sync(0xFFFFFFFFu, pa[j], mask);
                pb[j] += __shfl_xor_sync(0xFFFFFFFFu, pb[j], mask);
            }
        }
        float za = b7v, zb = b7v;
        #pragma unroll
        for (int j = 0; j < 4; ++j) {
            za += fmaxf(pa[j] + b6s[j], 0.f) * W7s[j];
            zb += fmaxf(pb[j] + b6s[j], 0.f) * W7s[j];
        }
        if (t == 0) {
            float* o = out + row0;
            o[g]     = 1.0f / (1.0f + __expf(-za));
            o[g + 8] = 1.0f / (1.0f + __expf(-zb));
        }
    }
}

// ============================ launch ============================
extern "C" void kernel_launch(void* const* d_in, const int* in_sizes, int n_in,
                              void* d_out, int out_size) {
    cudaFuncSetAttribute(fused_mlp_kernel,
                         cudaFuncAttributeMaxDynamicSharedMemorySize, SMEM_BYTES);
    fused_mlp_kernel<<<NCTAS, NTHREADS, SMEM_BYTES>>>(
        (const float*)d_in[0],
        (const float*)d_in[1],  (const float*)d_in[2],
        (const float*)d_in[3],  (const float*)d_in[4],
        (const float*)d_in[5],  (const float*)d_in[6],
        (const float*)d_in[7],  (const float*)d_in[8],
        (const float*)d_in[9],  (const float*)d_in[10],
        (const float*)d_in[11], (const float*)d_in[12],
        (const float*)d_in[13], (const float*)d_in[14],
        (float*)d_out);
}